// round 4
// baseline (speedup 1.0000x reference)
#include <cuda_runtime.h>
#include <cuda_bf16.h>
#include <math.h>

#define BMAX 4096
#define KR 800           // real K padded: 784 -> 800 (25 * 32)
#define KP2 1600         // row length: [Ah(800) | Al(800)]
#define NIT 25

// scratch (no allocations allowed)
__device__ __nv_bfloat16 g_A[BMAX * KP2];     // [Ah | Al] per row
__device__ __nv_bfloat16 g_B[256 * KP2];      // [Bh | Bl] per row
__device__ float g_h[BMAX * 256];
__device__ float g_vc[8];
__device__ float g_vs[8];

// ---------------------------------------------------------------------------
__device__ __forceinline__ void split_bf16(float x, __nv_bfloat16& h, __nv_bfloat16& l) {
    h = __float2bfloat16(x);
    l = __float2bfloat16(x - __bfloat162float(h));
}

// ---------------------------------------------------------------------------
__global__ void var_precompute_kernel(const float* __restrict__ var) {
    int i = threadIdx.x;
    if (i < 8) {
        float h = 0.5f * var[i];
        g_vc[i] = cosf(h);
        g_vs[i] = sinf(h);
    }
}

// ---------------------------------------------------------------------------
// Convert W1 [256][784] fp32 -> g_B split layout [Bh(800)|Bl(800)].
// ---------------------------------------------------------------------------
__global__ __launch_bounds__(256) void convert_w1_kernel(const float* __restrict__ W1) {
    int t = blockIdx.x * 256 + threadIdx.x;
    if (t >= 256 * 196) return;
    int n = t / 196;
    int kq = t - n * 196;
    int k = kq * 4;

    float4 w = *(const float4*)(W1 + n * 784 + k);
    __nv_bfloat16 h[4], l[4];
    split_bf16(w.x, h[0], l[0]);
    split_bf16(w.y, h[1], l[1]);
    split_bf16(w.z, h[2], l[2]);
    split_bf16(w.w, h[3], l[3]);

    uint2 hp, lp;
    {
        __nv_bfloat162 a(h[0], h[1]), b(h[2], h[3]);
        hp.x = *(unsigned*)&a; hp.y = *(unsigned*)&b;
        __nv_bfloat162 c(l[0], l[1]), d(l[2], l[3]);
        lp.x = *(unsigned*)&c; lp.y = *(unsigned*)&d;
    }
    __nv_bfloat16* row = g_B + n * KP2;
    *(uint2*)(row + k)       = hp;   // Bh
    *(uint2*)(row + KR + k)  = lp;   // Bl
    if (kq < 4) {
        *(uint2*)(row + 784 + kq * 4)      = make_uint2(0u, 0u);  // pad Bh
        *(uint2*)(row + KR + 784 + kq * 4) = make_uint2(0u, 0u);  // pad Bl
    }
}

// ---------------------------------------------------------------------------
// Quanvolution: one thread = one (batch, patch). 16-amplitude exact sim in
// registers. Writes split-bf16 features into [Ah|Al] layout.
// ---------------------------------------------------------------------------
__global__ void quanv_kernel(const float* __restrict__ x, int B) {
    int idx = blockIdx.x * blockDim.x + threadIdx.x;
    if (idx >= B * 196) return;
    int b = idx / 196;
    int p = idx - b * 196;
    int r = p / 14;
    int c = p - r * 14;

    const float* img = x + b * 784;
    float2 top = *(const float2*)(img + (2 * r) * 28 + 2 * c);
    float2 bot = *(const float2*)(img + (2 * r + 1) * 28 + 2 * c);
    float ang[4] = {top.x, top.y, bot.x, bot.y};

    float ec[4], es[4];
#pragma unroll
    for (int w = 0; w < 4; ++w) sincosf(0.5f * ang[w], &es[w], &ec[w]);

    float st[16];
#pragma unroll
    for (int i = 0; i < 16; ++i) {
        st[i] = ((i & 8) ? es[0] : ec[0]) * ((i & 4) ? es[1] : ec[1]) *
                ((i & 2) ? es[2] : ec[2]) * ((i & 1) ? es[3] : ec[3]);
    }

    float vc[8], vs[8];
#pragma unroll
    for (int i = 0; i < 8; ++i) { vc[i] = g_vc[i]; vs[i] = g_vs[i]; }

#pragma unroll
    for (int d = 0; d < 2; ++d) {
#pragma unroll
        for (int w = 0; w < 4; ++w) {
            float cc = vc[d * 4 + w];
            float ss = vs[d * 4 + w];
            int mask = 8 >> w;
#pragma unroll
            for (int i = 0; i < 16; ++i) {
                if (!(i & mask)) {
                    int j = i | mask;
                    float a = st[i], bb = st[j];
                    st[i] = cc * a - ss * bb;
                    st[j] = ss * a + cc * bb;
                }
            }
        }
#pragma unroll
        for (int cw = 0; cw < 4; ++cw) {
            int tw = (cw + 1) & 3;
            int cm = 8 >> cw;
            int tm = 8 >> tw;
#pragma unroll
            for (int i = 0; i < 16; ++i) {
                if ((i & cm) && !(i & tm)) {
                    int j = i | tm;
                    float t = st[i]; st[i] = st[j]; st[j] = t;
                }
            }
        }
    }

    float q[16];
#pragma unroll
    for (int i = 0; i < 16; ++i) q[i] = st[i] * st[i];

    float fo[4];
#pragma unroll
    for (int w = 0; w < 4; ++w) {
        int m = 8 >> w;
        float acc = 0.f;
#pragma unroll
        for (int i = 0; i < 16; ++i) acc += (i & m) ? -q[i] : q[i];
        fo[w] = acc;
    }

    __nv_bfloat16 fh[4], fl[4];
#pragma unroll
    for (int w = 0; w < 4; ++w) split_bf16(fo[w], fh[w], fl[w]);

    uint2 hp, lp;
    {
        __nv_bfloat162 a(fh[0], fh[1]), bb(fh[2], fh[3]);
        hp.x = *(unsigned*)&a; hp.y = *(unsigned*)&bb;
        __nv_bfloat162 cc(fl[0], fl[1]), dd(fl[2], fl[3]);
        lp.x = *(unsigned*)&cc; lp.y = *(unsigned*)&dd;
    }
    __nv_bfloat16* row = g_A + (size_t)b * KP2;
    *(uint2*)(row + p * 4)      = hp;   // Ah
    *(uint2*)(row + KR + p * 4) = lp;   // Al
    if (p < 4) {
        *(uint2*)(row + 784 + p * 4)      = make_uint2(0u, 0u);
        *(uint2*)(row + KR + 784 + p * 4) = make_uint2(0u, 0u);
    }
}

// ---------------------------------------------------------------------------
// Tensor-core GEMM1: h = relu(Ah·Bh + Ah·Bl + Al·Bh + b1).
// BM=64, BN=64, BK=32(real), 4 warps (2x2), warp tile 32x32, 3-stage cp.async.
// ---------------------------------------------------------------------------
#define ST 40   // padded row stride: conflict-free ldmatrix (80B row)

__device__ __forceinline__ void mma_bf16(float* c, const unsigned* a, const unsigned* b) {
    asm volatile(
        "mma.sync.aligned.m16n8k16.row.col.f32.bf16.bf16.f32 "
        "{%0,%1,%2,%3}, {%4,%5,%6,%7}, {%8,%9}, {%0,%1,%2,%3};\n"
        : "+f"(c[0]), "+f"(c[1]), "+f"(c[2]), "+f"(c[3])
        : "r"(a[0]), "r"(a[1]), "r"(a[2]), "r"(a[3]), "r"(b[0]), "r"(b[1]));
}

__global__ __launch_bounds__(128) void gemm1_kernel(const float* __restrict__ b1) {
    __shared__ __nv_bfloat16 Ah_s[3][64][ST];
    __shared__ __nv_bfloat16 Al_s[3][64][ST];
    __shared__ __nv_bfloat16 Bh_s[3][64][ST];
    __shared__ __nv_bfloat16 Bl_s[3][64][ST];

    int tid = threadIdx.x;
    int wid = tid >> 5;
    int lane = tid & 31;
    int warp_m = wid & 1;      // 0..1 -> m offset 32*warp_m
    int warp_n = wid >> 1;     // 0..1 -> n offset 32*warp_n
    int bm = blockIdx.x * 64;
    int bn = blockIdx.y * 64;

    float acc[2][4][4];
#pragma unroll
    for (int i = 0; i < 2; ++i)
#pragma unroll
        for (int j = 0; j < 4; ++j)
#pragma unroll
            for (int k = 0; k < 4; ++k) acc[i][j][k] = 0.f;

    // load mapping: 64 rows x 4 chunks(16B) = 256 chunks per tile; 128 thr x 2
    int r0 = tid >> 1;                 // id = tid: rows 0..63 (chunk 0/1)
    int c0 = (tid & 1);                // chunks 0..1
    int r1 = (tid + 128) >> 1;         // wait — recompute below
    (void)r1;
    // chunk ids: tid and tid+128.  row = id>>2, colc = id&3
    int la_r0 = tid >> 2, la_c0 = tid & 3;
    int la_r1 = (tid + 128) >> 2, la_c1 = (tid + 128) & 3;
    (void)r0; (void)c0;

#define CPA(dst, src) asm volatile("cp.async.cg.shared.global [%0], [%1], 16;\n" ::"r"(dst), "l"(src))

#define LOAD_STAGE(IT, BUF)                                                              \
    do {                                                                                 \
        int k0 = (IT) * 32;                                                              \
        const __nv_bfloat16* arow0 = g_A + (size_t)(bm + la_r0) * KP2 + k0 + la_c0 * 8;  \
        const __nv_bfloat16* arow1 = g_A + (size_t)(bm + la_r1) * KP2 + k0 + la_c1 * 8;  \
        const __nv_bfloat16* brow0 = g_B + (size_t)(bn + la_r0) * KP2 + k0 + la_c0 * 8;  \
        const __nv_bfloat16* brow1 = g_B + (size_t)(bn + la_r1) * KP2 + k0 + la_c1 * 8;  \
        CPA((unsigned)__cvta_generic_to_shared(&Ah_s[BUF][la_r0][la_c0 * 8]), arow0);    \
        CPA((unsigned)__cvta_generic_to_shared(&Ah_s[BUF][la_r1][la_c1 * 8]), arow1);    \
        CPA((unsigned)__cvta_generic_to_shared(&Al_s[BUF][la_r0][la_c0 * 8]), arow0 + KR); \
        CPA((unsigned)__cvta_generic_to_shared(&Al_s[BUF][la_r1][la_c1 * 8]), arow1 + KR); \
        CPA((unsigned)__cvta_generic_to_shared(&Bh_s[BUF][la_r0][la_c0 * 8]), brow0);    \
        CPA((unsigned)__cvta_generic_to_shared(&Bh_s[BUF][la_r1][la_c1 * 8]), brow1);    \
        CPA((unsigned)__cvta_generic_to_shared(&Bl_s[BUF][la_r0][la_c0 * 8]), brow0 + KR); \
        CPA((unsigned)__cvta_generic_to_shared(&Bl_s[BUF][la_r1][la_c1 * 8]), brow1 + KR); \
    } while (0)

    LOAD_STAGE(0, 0);
    asm volatile("cp.async.commit_group;\n" ::);
    LOAD_STAGE(1, 1);
    asm volatile("cp.async.commit_group;\n" ::);

    int gid = lane >> 3;
    int wi = lane & 7;

    for (int it = 0; it < NIT; ++it) {
        int buf = it % 3;
        asm volatile("cp.async.wait_group 1;\n" ::);
        __syncthreads();

        if (it + 2 < NIT) LOAD_STAGE(it + 2, (it + 2) % 3);
        asm volatile("cp.async.commit_group;\n" ::);

#pragma unroll
        for (int kk = 0; kk < 2; ++kk) {
            unsigned ah[2][4], al[2][4];
#pragma unroll
            for (int mf = 0; mf < 2; ++mf) {
                int row = warp_m * 32 + mf * 16 + (gid & 1) * 8 + wi;
                int col = kk * 16 + (gid >> 1) * 8;
                unsigned addr = (unsigned)__cvta_generic_to_shared(&Ah_s[buf][row][col]);
                asm volatile(
                    "ldmatrix.sync.aligned.m8n8.x4.shared.b16 {%0,%1,%2,%3}, [%4];\n"
                    : "=r"(ah[mf][0]), "=r"(ah[mf][1]), "=r"(ah[mf][2]), "=r"(ah[mf][3])
                    : "r"(addr));
                unsigned addr2 = (unsigned)__cvta_generic_to_shared(&Al_s[buf][row][col]);
                asm volatile(
                    "ldmatrix.sync.aligned.m8n8.x4.shared.b16 {%0,%1,%2,%3}, [%4];\n"
                    : "=r"(al[mf][0]), "=r"(al[mf][1]), "=r"(al[mf][2]), "=r"(al[mf][3])
                    : "r"(addr2));
            }
            unsigned bh[4][2], bl[4][2];
#pragma unroll
            for (int nh = 0; nh < 2; ++nh) {
                int row = warp_n * 32 + nh * 16 + (gid >> 1) * 8 + wi;
                int col = kk * 16 + (gid & 1) * 8;
                unsigned addr = (unsigned)__cvta_generic_to_shared(&Bh_s[buf][row][col]);
                asm volatile(
                    "ldmatrix.sync.aligned.m8n8.x4.shared.b16 {%0,%1,%2,%3}, [%4];\n"
                    : "=r"(bh[2 * nh][0]), "=r"(bh[2 * nh][1]),
                      "=r"(bh[2 * nh + 1][0]), "=r"(bh[2 * nh + 1][1])
                    : "r"(addr));
                unsigned addr2 = (unsigned)__cvta_generic_to_shared(&Bl_s[buf][row][col]);
                asm volatile(
                    "ldmatrix.sync.aligned.m8n8.x4.shared.b16 {%0,%1,%2,%3}, [%4];\n"
                    : "=r"(bl[2 * nh][0]), "=r"(bl[2 * nh][1]),
                      "=r"(bl[2 * nh + 1][0]), "=r"(bl[2 * nh + 1][1])
                    : "r"(addr2));
            }
#pragma unroll
            for (int mf = 0; mf < 2; ++mf)
#pragma unroll
                for (int nf = 0; nf < 4; ++nf) {
                    mma_bf16(acc[mf][nf], ah[mf], bh[nf]);
                    mma_bf16(acc[mf][nf], ah[mf], bl[nf]);
                    mma_bf16(acc[mf][nf], al[mf], bh[nf]);
                }
        }
    }

    // epilogue: bias + relu, fp32 out
#pragma unroll
    for (int nf = 0; nf < 4; ++nf) {
        int n = bn + warp_n * 32 + nf * 8 + (lane & 3) * 2;
        float2 bias = *(const float2*)(b1 + n);
#pragma unroll
        for (int mf = 0; mf < 2; ++mf) {
            int m = bm + warp_m * 32 + mf * 16 + (lane >> 2);
            float2 o0, o1;
            o0.x = fmaxf(acc[mf][nf][0] + bias.x, 0.f);
            o0.y = fmaxf(acc[mf][nf][1] + bias.y, 0.f);
            o1.x = fmaxf(acc[mf][nf][2] + bias.x, 0.f);
            o1.y = fmaxf(acc[mf][nf][3] + bias.y, 0.f);
            *(float2*)(g_h + m * 256 + n) = o0;
            *(float2*)(g_h + (m + 8) * 256 + n) = o1;
        }
    }
#undef LOAD_STAGE
#undef CPA
}

// ---------------------------------------------------------------------------
// Head: logits = h @ W2^T + b2, then log_softmax. 4 rows per warp.
// ---------------------------------------------------------------------------
__global__ __launch_bounds__(256) void head_kernel(const float* __restrict__ W2,
                                                   const float* __restrict__ b2,
                                                   float* __restrict__ out, int B) {
    int warp = threadIdx.x >> 5;
    int lane = threadIdx.x & 31;
    int row0 = (blockIdx.x * 8 + warp) * 4;
    if (row0 >= B) return;

    float hv[4][8];
#pragma unroll
    for (int r = 0; r < 4; ++r)
#pragma unroll
        for (int j = 0; j < 8; ++j) hv[r][j] = g_h[(row0 + r) * 256 + lane + 32 * j];

    float lg[4][10];
#pragma unroll
    for (int o = 0; o < 10; ++o) {
        const float* w = W2 + o * 256;
        float wv[8];
#pragma unroll
        for (int j = 0; j < 8; ++j) wv[j] = __ldg(w + lane + 32 * j);
        float p[4] = {0.f, 0.f, 0.f, 0.f};
#pragma unroll
        for (int j = 0; j < 8; ++j)
#pragma unroll
            for (int r = 0; r < 4; ++r) p[r] += hv[r][j] * wv[j];
#pragma unroll
        for (int off = 16; off > 0; off >>= 1)
#pragma unroll
            for (int r = 0; r < 4; ++r) p[r] += __shfl_xor_sync(0xffffffffu, p[r], off);
        float bo = __ldg(b2 + o);
#pragma unroll
        for (int r = 0; r < 4; ++r) lg[r][o] = p[r] + bo;
    }

#pragma unroll
    for (int r = 0; r < 4; ++r) {
        float m = lg[r][0];
#pragma unroll
        for (int o = 1; o < 10; ++o) m = fmaxf(m, lg[r][o]);
        float sum = 0.f;
#pragma unroll
        for (int o = 0; o < 10; ++o) sum += expf(lg[r][o] - m);
        float lse = m + logf(sum);
        float myv = 0.f;
#pragma unroll
        for (int o = 0; o < 10; ++o)
            if (lane == o) myv = lg[r][o];
        if (lane < 10) out[(row0 + r) * 10 + lane] = myv - lse;
    }
}

// ---------------------------------------------------------------------------
extern "C" void kernel_launch(void* const* d_in, const int* in_sizes, int n_in,
                              void* d_out, int out_size) {
    const float* x   = (const float*)d_in[0];
    const float* var = (const float*)d_in[1];
    const float* W1  = (const float*)d_in[2];
    const float* b1  = (const float*)d_in[3];
    const float* W2  = (const float*)d_in[4];
    const float* b2  = (const float*)d_in[5];
    float* out = (float*)d_out;

    int B = in_sizes[0] / 784;

    var_precompute_kernel<<<1, 8>>>(var);
    convert_w1_kernel<<<(256 * 196 + 255) / 256, 256>>>(W1);

    int np = B * 196;
    quanv_kernel<<<(np + 255) / 256, 256>>>(x, B);

    dim3 g1(B / 64, 256 / 64);
    gemm1_kernel<<<g1, 128>>>(b1);

    // 8 warps/block, 4 rows/warp -> 32 rows per block
    int head_blocks = (B / 4 + 7) / 8;
    head_kernel<<<head_blocks, 256>>>(W2, b2, out, B);
}

// round 6
// speedup vs baseline: 1.4815x; 1.4815x over previous
#include <cuda_runtime.h>
#include <cuda_bf16.h>
#include <math.h>

#define BMAX 4096
#define KP 2368          // 3*784 = 2352, padded to 74*32

// scratch (no allocations allowed)
__device__ __nv_bfloat16 g_A[BMAX * KP];      // [Ah | Ah | Al] per row, padded
__device__ __nv_bfloat16 g_B[256 * KP];       // [Bh | Bl | Bh] per row, padded
__device__ float g_h[BMAX * 256];
__device__ float g_vc[8];
__device__ float g_vs[8];

// ---------------------------------------------------------------------------
__device__ __forceinline__ void split_bf16(float x, __nv_bfloat16& h, __nv_bfloat16& l) {
    h = __float2bfloat16(x);
    l = __float2bfloat16(x - __bfloat162float(h));
}

// ---------------------------------------------------------------------------
__global__ void var_precompute_kernel(const float* __restrict__ var) {
    int i = threadIdx.x;
    if (i < 8) {
        float h = 0.5f * var[i];
        g_vc[i] = cosf(h);
        g_vs[i] = sinf(h);
    }
}

// ---------------------------------------------------------------------------
// Convert W1 [256][784] fp32 -> g_B split-bf16 layout. Each thread: 4 k's.
// ---------------------------------------------------------------------------
__global__ __launch_bounds__(256) void convert_w1_kernel(const float* __restrict__ W1) {
    int t = blockIdx.x * 256 + threadIdx.x;
    if (t >= 256 * 196) return;
    int n = t / 196;
    int kq = t - n * 196;
    int k = kq * 4;

    float4 w = *(const float4*)(W1 + n * 784 + k);
    __nv_bfloat16 h[4], l[4];
    split_bf16(w.x, h[0], l[0]);
    split_bf16(w.y, h[1], l[1]);
    split_bf16(w.z, h[2], l[2]);
    split_bf16(w.w, h[3], l[3]);

    uint2 hp, lp;
    {
        __nv_bfloat162 a(h[0], h[1]), b(h[2], h[3]);
        hp.x = *(unsigned*)&a; hp.y = *(unsigned*)&b;
        __nv_bfloat162 c(l[0], l[1]), d(l[2], l[3]);
        lp.x = *(unsigned*)&c; lp.y = *(unsigned*)&d;
    }
    __nv_bfloat16* row = g_B + n * KP;
    *(uint2*)(row + k)        = hp;   // Bh
    *(uint2*)(row + 784 + k)  = lp;   // Bl
    *(uint2*)(row + 1568 + k) = hp;   // Bh
    if (kq < 4) {
        *(uint2*)(row + 2352 + kq * 4) = make_uint2(0u, 0u);  // pad
    }
}

// ---------------------------------------------------------------------------
// Quanvolution: one thread = one (batch, patch). 16-amplitude exact sim in
// registers. Writes split-bf16 features into the A_cat layout.
// ---------------------------------------------------------------------------
__global__ void quanv_kernel(const float* __restrict__ x, int B) {
    int idx = blockIdx.x * blockDim.x + threadIdx.x;
    if (idx >= B * 196) return;
    int b = idx / 196;
    int p = idx - b * 196;
    int r = p / 14;
    int c = p - r * 14;

    const float* img = x + b * 784;
    float2 top = *(const float2*)(img + (2 * r) * 28 + 2 * c);
    float2 bot = *(const float2*)(img + (2 * r + 1) * 28 + 2 * c);
    float ang[4] = {top.x, top.y, bot.x, bot.y};

    float ec[4], es[4];
#pragma unroll
    for (int w = 0; w < 4; ++w) sincosf(0.5f * ang[w], &es[w], &ec[w]);

    float st[16];
#pragma unroll
    for (int i = 0; i < 16; ++i) {
        st[i] = ((i & 8) ? es[0] : ec[0]) * ((i & 4) ? es[1] : ec[1]) *
                ((i & 2) ? es[2] : ec[2]) * ((i & 1) ? es[3] : ec[3]);
    }

    float vc[8], vs[8];
#pragma unroll
    for (int i = 0; i < 8; ++i) { vc[i] = g_vc[i]; vs[i] = g_vs[i]; }

#pragma unroll
    for (int d = 0; d < 2; ++d) {
#pragma unroll
        for (int w = 0; w < 4; ++w) {
            float cc = vc[d * 4 + w];
            float ss = vs[d * 4 + w];
            int mask = 8 >> w;
#pragma unroll
            for (int i = 0; i < 16; ++i) {
                if (!(i & mask)) {
                    int j = i | mask;
                    float a = st[i], bb = st[j];
                    st[i] = cc * a - ss * bb;
                    st[j] = ss * a + cc * bb;
                }
            }
        }
#pragma unroll
        for (int cw = 0; cw < 4; ++cw) {
            int tw = (cw + 1) & 3;
            int cm = 8 >> cw;
            int tm = 8 >> tw;
#pragma unroll
            for (int i = 0; i < 16; ++i) {
                if ((i & cm) && !(i & tm)) {
                    int j = i | tm;
                    float t = st[i]; st[i] = st[j]; st[j] = t;
                }
            }
        }
    }

    float q[16];
#pragma unroll
    for (int i = 0; i < 16; ++i) q[i] = st[i] * st[i];

    float fo[4];
#pragma unroll
    for (int w = 0; w < 4; ++w) {
        int m = 8 >> w;
        float acc = 0.f;
#pragma unroll
        for (int i = 0; i < 16; ++i) acc += (i & m) ? -q[i] : q[i];
        fo[w] = acc;
    }

    __nv_bfloat16 fh[4], fl[4];
#pragma unroll
    for (int w = 0; w < 4; ++w) split_bf16(fo[w], fh[w], fl[w]);

    uint2 hp, lp;
    {
        __nv_bfloat162 a(fh[0], fh[1]), bb(fh[2], fh[3]);
        hp.x = *(unsigned*)&a; hp.y = *(unsigned*)&bb;
        __nv_bfloat162 cc(fl[0], fl[1]), dd(fl[2], fl[3]);
        lp.x = *(unsigned*)&cc; lp.y = *(unsigned*)&dd;
    }
    __nv_bfloat16* row = g_A + (size_t)b * KP;
    *(uint2*)(row + p * 4)        = hp;   // Ah
    *(uint2*)(row + 784 + p * 4)  = hp;   // Ah (pairs Bl)
    *(uint2*)(row + 1568 + p * 4) = lp;   // Al (pairs Bh)
    if (p < 4) {
        *(uint2*)(row + 2352 + p * 4) = make_uint2(0u, 0u);  // pad
    }
}

// ---------------------------------------------------------------------------
// Tensor-core GEMM1: h = relu(A_cat @ B_cat^T + b1).  M=B, N=256, K=KP (bf16).
// BM=128, BN=64, BK=32, 8 warps (4x2), warp tile 32x32 via m16n8k16 mma.
// 3-stage cp.async pipeline, ONE __syncthreads per k-iteration.
// ---------------------------------------------------------------------------
#define GBK 32
#define NITER (KP / GBK)   // 74
#define ASTRIDE 40         // padded row (conflict-free ldmatrix: 80B stride)

__device__ __forceinline__ void mma_bf16(float* c, const unsigned* a, const unsigned* b) {
    asm volatile(
        "mma.sync.aligned.m16n8k16.row.col.f32.bf16.bf16.f32 "
        "{%0,%1,%2,%3}, {%4,%5,%6,%7}, {%8,%9}, {%0,%1,%2,%3};\n"
        : "+f"(c[0]), "+f"(c[1]), "+f"(c[2]), "+f"(c[3])
        : "r"(a[0]), "r"(a[1]), "r"(a[2]), "r"(a[3]), "r"(b[0]), "r"(b[1]));
}

__global__ __launch_bounds__(256, 1) void gemm1_kernel(const float* __restrict__ b1) {
    __shared__ __nv_bfloat16 As[3][128][ASTRIDE];   // 30.7 KB
    __shared__ __nv_bfloat16 Bs[3][64][ASTRIDE];    // 15.4 KB  (total 46 KB)

    int tid = threadIdx.x;
    int wid = tid >> 5;
    int lane = tid & 31;
    int warp_m = wid & 3;      // 0..3 -> m offset 32*warp_m
    int warp_n = wid >> 2;     // 0..1 -> n offset 32*warp_n
    int bm = blockIdx.x * 128;
    int bn = blockIdx.y * 64;

    float acc[2][4][4];
#pragma unroll
    for (int i = 0; i < 2; ++i)
#pragma unroll
        for (int j = 0; j < 4; ++j)
#pragma unroll
            for (int k = 0; k < 4; ++k) acc[i][j][k] = 0.f;

    // load-thread mapping: A = 128 rows x 4 chunks(16B), B = 64 rows x 4 chunks
    int a_r0 = tid >> 2;          // rows 0..63
    int a_c0 = tid & 3;
    int a_r1 = (tid + 256) >> 2;  // rows 64..127
    int a_c1 = a_c0;
    int b_r = tid >> 2;
    int b_c = tid & 3;

#define LOAD_STAGE(IT, BUF)                                                      \
    do {                                                                         \
        int k0 = (IT) * GBK;                                                     \
        const __nv_bfloat16* s0 = g_A + (size_t)(bm + a_r0) * KP + k0 + a_c0*8;  \
        unsigned d0 = (unsigned)__cvta_generic_to_shared(&As[BUF][a_r0][a_c0*8]);\
        asm volatile("cp.async.cg.shared.global [%0], [%1], 16;\n" ::"r"(d0), "l"(s0)); \
        const __nv_bfloat16* s1 = g_A + (size_t)(bm + a_r1) * KP + k0 + a_c1*8;  \
        unsigned d1 = (unsigned)__cvta_generic_to_shared(&As[BUF][a_r1][a_c1*8]);\
        asm volatile("cp.async.cg.shared.global [%0], [%1], 16;\n" ::"r"(d1), "l"(s1)); \
        const __nv_bfloat16* s2 = g_B + (size_t)(bn + b_r) * KP + k0 + b_c*8;    \
        unsigned d2 = (unsigned)__cvta_generic_to_shared(&Bs[BUF][b_r][b_c*8]);  \
        asm volatile("cp.async.cg.shared.global [%0], [%1], 16;\n" ::"r"(d2), "l"(s2)); \
    } while (0)

    LOAD_STAGE(0, 0);
    asm volatile("cp.async.commit_group;\n" ::);
    LOAD_STAGE(1, 1);
    asm volatile("cp.async.commit_group;\n" ::);

    int gid = lane >> 3;   // ldmatrix address group
    int wi = lane & 7;

    for (int it = 0; it < NITER; ++it) {
        int buf = it % 3;
        asm volatile("cp.async.wait_group 1;\n" ::);
        __syncthreads();   // stage `buf` ready; compute of it-1 fully retired

        // refill stage it+2 into buffer (it+2)%3 == (it-1)%3 (safe post-sync)
        if (it + 2 < NITER) LOAD_STAGE(it + 2, (it + 2) % 3);
        asm volatile("cp.async.commit_group;\n" ::);

#pragma unroll
        for (int kk = 0; kk < 2; ++kk) {
            unsigned a[2][4];
#pragma unroll
            for (int mf = 0; mf < 2; ++mf) {
                int row = warp_m * 32 + mf * 16 + (gid & 1) * 8 + wi;
                int col = kk * 16 + (gid >> 1) * 8;
                unsigned addr = (unsigned)__cvta_generic_to_shared(&As[buf][row][col]);
                asm volatile(
                    "ldmatrix.sync.aligned.m8n8.x4.shared.b16 {%0,%1,%2,%3}, [%4];\n"
                    : "=r"(a[mf][0]), "=r"(a[mf][1]), "=r"(a[mf][2]), "=r"(a[mf][3])
                    : "r"(addr));
            }
            unsigned b[4][2];
#pragma unroll
            for (int nh = 0; nh < 2; ++nh) {
                int row = warp_n * 32 + nh * 16 + (gid >> 1) * 8 + wi;
                int col = kk * 16 + (gid & 1) * 8;
                unsigned addr = (unsigned)__cvta_generic_to_shared(&Bs[buf][row][col]);
                asm volatile(
                    "ldmatrix.sync.aligned.m8n8.x4.shared.b16 {%0,%1,%2,%3}, [%4];\n"
                    : "=r"(b[2 * nh][0]), "=r"(b[2 * nh][1]),
                      "=r"(b[2 * nh + 1][0]), "=r"(b[2 * nh + 1][1])
                    : "r"(addr));
            }
#pragma unroll
            for (int mf = 0; mf < 2; ++mf)
#pragma unroll
                for (int nf = 0; nf < 4; ++nf) mma_bf16(acc[mf][nf], a[mf], b[nf]);
        }
        // no trailing sync: next iteration's top sync protects buffer reuse
    }

    // epilogue: bias + relu, fp32 out
#pragma unroll
    for (int nf = 0; nf < 4; ++nf) {
        int n = bn + warp_n * 32 + nf * 8 + (lane & 3) * 2;
        float2 bias = *(const float2*)(b1 + n);
#pragma unroll
        for (int mf = 0; mf < 2; ++mf) {
            int m = bm + warp_m * 32 + mf * 16 + (lane >> 2);
            float2 o0, o1;
            o0.x = fmaxf(acc[mf][nf][0] + bias.x, 0.f);
            o0.y = fmaxf(acc[mf][nf][1] + bias.y, 0.f);
            o1.x = fmaxf(acc[mf][nf][2] + bias.x, 0.f);
            o1.y = fmaxf(acc[mf][nf][3] + bias.y, 0.f);
            *(float2*)(g_h + m * 256 + n) = o0;
            *(float2*)(g_h + (m + 8) * 256 + n) = o1;
        }
    }
#undef LOAD_STAGE
}

// ---------------------------------------------------------------------------
// Head: logits = h @ W2^T + b2, then log_softmax. 4 rows per warp.
// ---------------------------------------------------------------------------
__global__ __launch_bounds__(256) void head_kernel(const float* __restrict__ W2,
                                                   const float* __restrict__ b2,
                                                   float* __restrict__ out, int B) {
    int warp = threadIdx.x >> 5;
    int lane = threadIdx.x & 31;
    int row0 = (blockIdx.x * 8 + warp) * 4;
    if (row0 >= B) return;

    float hv[4][8];
#pragma unroll
    for (int r = 0; r < 4; ++r)
#pragma unroll
        for (int j = 0; j < 8; ++j) hv[r][j] = g_h[(row0 + r) * 256 + lane + 32 * j];

    float lg[4][10];
#pragma unroll
    for (int o = 0; o < 10; ++o) {
        const float* w = W2 + o * 256;
        float wv[8];
#pragma unroll
        for (int j = 0; j < 8; ++j) wv[j] = __ldg(w + lane + 32 * j);
        float p[4] = {0.f, 0.f, 0.f, 0.f};
#pragma unroll
        for (int j = 0; j < 8; ++j)
#pragma unroll
            for (int r = 0; r < 4; ++r) p[r] += hv[r][j] * wv[j];
#pragma unroll
        for (int off = 16; off > 0; off >>= 1)
#pragma unroll
            for (int r = 0; r < 4; ++r) p[r] += __shfl_xor_sync(0xffffffffu, p[r], off);
        float bo = __ldg(b2 + o);
#pragma unroll
        for (int r = 0; r < 4; ++r) lg[r][o] = p[r] + bo;
    }

#pragma unroll
    for (int r = 0; r < 4; ++r) {
        float m = lg[r][0];
#pragma unroll
        for (int o = 1; o < 10; ++o) m = fmaxf(m, lg[r][o]);
        float sum = 0.f;
#pragma unroll
        for (int o = 0; o < 10; ++o) sum += expf(lg[r][o] - m);
        float lse = m + logf(sum);
        float myv = 0.f;
#pragma unroll
        for (int o = 0; o < 10; ++o)
            if (lane == o) myv = lg[r][o];
        if (lane < 10) out[(row0 + r) * 10 + lane] = myv - lse;
    }
}

// ---------------------------------------------------------------------------
extern "C" void kernel_launch(void* const* d_in, const int* in_sizes, int n_in,
                              void* d_out, int out_size) {
    const float* x   = (const float*)d_in[0];
    const float* var = (const float*)d_in[1];
    const float* W1  = (const float*)d_in[2];
    const float* b1  = (const float*)d_in[3];
    const float* W2  = (const float*)d_in[4];
    const float* b2  = (const float*)d_in[5];
    float* out = (float*)d_out;

    int B = in_sizes[0] / 784;

    var_precompute_kernel<<<1, 8>>>(var);
    convert_w1_kernel<<<(256 * 196 + 255) / 256, 256>>>(W1);

    int np = B * 196;
    quanv_kernel<<<(np + 255) / 256, 256>>>(x, B);

    dim3 g1(B / 128, 256 / 64);
    gemm1_kernel<<<g1, 256>>>(b1);

    // 8 warps/block, 4 rows/warp -> 32 rows per block
    int head_blocks = (B / 4 + 7) / 8;
    head_kernel<<<head_blocks, 256>>>(W2, b2, out, B);
}